// round 10
// baseline (speedup 1.0000x reference)
#include <cuda_runtime.h>
#include <cuda_fp16.h>
#include <math.h>
#include <stdint.h>

#define NN 50000
#define NE 1600000
#define CH 128
#define FE 50
#define TS 132
#define NTAB 16384

__device__ __half2 g_h2[(size_t)NN * 64];            // h in fp16, packed pairs
__device__ float g_agg[(size_t)NN * CH];
__device__ float g_table[(size_t)(NTAB + 1) * CH];
__device__ __half2 g_tab2[(size_t)NTAB * CH];
__device__ float4 g_Wp0[8192];   // W_lin  (fragment-packed tf32 hi/lo)
__device__ float4 g_Wp1[8192];   // Wm1
__device__ float4 g_Wp2[8192];   // Wm2
// receiver-CSR
__device__ int   g_count[NN];
__device__ int   g_base[NN + 1];
__device__ int   g_cursor[NN];
__device__ uint2 g_rec[NE];      // {sender, (i<<16)|f_q16} in CSR order

__device__ __forceinline__ float ssp(float x) {
    return fmaxf(x, 0.0f) + log1pf(__expf(-fabsf(x))) - 0.69314718055994530942f;
}
__device__ __forceinline__ void split_tf32(float x, uint32_t& hi, uint32_t& lo) {
    asm("cvt.rna.tf32.f32 %0, %1;" : "=r"(hi) : "f"(x));
    float r = x - __uint_as_float(hi);
    asm("cvt.rna.tf32.f32 %0, %1;" : "=r"(lo) : "f"(r));
}
#define MMA(c, a0, a1, a2, a3, b0, b1)                                        \
    asm volatile("mma.sync.aligned.m16n8k8.row.col.f32.tf32.tf32.f32 "        \
                 "{%0,%1,%2,%3}, {%4,%5,%6,%7}, {%8,%9}, {%0,%1,%2,%3};"      \
                 : "+f"((c)[0]), "+f"((c)[1]), "+f"((c)[2]), "+f"((c)[3])     \
                 : "r"(a0), "r"(a1), "r"(a2), "r"(a3), "r"(b0), "r"(b1));

#define FMA8(ar, av, w0, w1)                 \
    ar[0] = fmaf(av, w0.x, ar[0]);           \
    ar[1] = fmaf(av, w0.y, ar[1]);           \
    ar[2] = fmaf(av, w0.z, ar[2]);           \
    ar[3] = fmaf(av, w0.w, ar[3]);           \
    ar[4] = fmaf(av, w1.x, ar[4]);           \
    ar[5] = fmaf(av, w1.y, ar[5]);           \
    ar[6] = fmaf(av, w1.z, ar[6]);           \
    ar[7] = fmaf(av, w1.w, ar[7]);

// ---------------------------------------------------------------------------
// CSR build
// ---------------------------------------------------------------------------
__global__ void zero_count_kernel() {
    int i = blockIdx.x * blockDim.x + threadIdx.x;
    if (i < NN) g_count[i] = 0;
}
__global__ void count_kernel(const int* __restrict__ receivers) {
    int stride = gridDim.x * blockDim.x;
    for (int e = blockIdx.x * blockDim.x + threadIdx.x; e < NE; e += stride)
        atomicAdd(&g_count[__ldg(receivers + e)], 1);
}
__global__ __launch_bounds__(1024, 1)
void scan_kernel() {
    __shared__ int ps[1024];
    const int tid = threadIdx.x;
    const int CHUNK = 49;                       // 1024*49 >= NN
    const int start = tid * CHUNK;
    int s = 0;
    #pragma unroll 1
    for (int k = 0; k < CHUNK; k++) {
        int idx = start + k;
        if (idx < NN) s += g_count[idx];
    }
    ps[tid] = s;
    __syncthreads();
    #pragma unroll
    for (int off = 1; off < 1024; off <<= 1) {
        int v = (tid >= off) ? ps[tid - off] : 0;
        __syncthreads();
        ps[tid] += v;
        __syncthreads();
    }
    int run = ps[tid] - s;                      // exclusive prefix
    #pragma unroll 1
    for (int k = 0; k < CHUNK; k++) {
        int idx = start + k;
        if (idx < NN) {
            g_base[idx] = run;
            g_cursor[idx] = run;
            run += g_count[idx];
        }
    }
    if (tid == 1023) g_base[NN] = ps[1023];
}
__global__ void fill_kernel(const float* __restrict__ dist,
                            const int* __restrict__ senders,
                            const int* __restrict__ receivers) {
    const float SCALE = (float)NTAB / 5.0f;
    int stride = gridDim.x * blockDim.x;
    for (int e = blockIdx.x * blockDim.x + threadIdx.x; e < NE; e += stride) {
        int r = __ldg(receivers + e);
        int s = __ldg(senders + e);
        float u = __ldg(dist + e) * SCALE;
        int i = (int)u;
        i = i < 0 ? 0 : (i > NTAB - 1 ? NTAB - 1 : i);
        float f = u - (float)i;
        uint32_t fq = (uint32_t)(f * 65536.0f);
        if (fq > 65535u) fq = 65535u;
        int pos = atomicAdd(&g_cursor[r], 1);
        g_rec[pos] = make_uint2((uint32_t)s, ((uint32_t)i << 16) | fq);
    }
}

// ---------------------------------------------------------------------------
// Gather-aggregate: warp per receiver node; fp32 register accumulation.
// ---------------------------------------------------------------------------
__global__ __launch_bounds__(256, 8)
void gather_kernel() {
    const int lane = threadIdx.x & 31;
    const int warp = (blockIdx.x * blockDim.x + threadIdx.x) >> 5;
    const int nwarps = (gridDim.x * blockDim.x) >> 5;

    for (int n = warp; n < NN; n += nwarps) {
        const int b0 = __ldg(g_base + n);
        const int b1 = __ldg(g_base + n + 1);
        float4 acc = make_float4(0.f, 0.f, 0.f, 0.f);

        if (b0 < b1) {
            // prefetch first edge
            uint2 rec = __ldg(g_rec + b0);
            uint4 tw = __ldg(reinterpret_cast<const uint4*>(
                g_tab2 + (size_t)(rec.y >> 16) * CH) + lane);
            uint2 hw = __ldg(reinterpret_cast<const uint2*>(
                g_h2 + (size_t)rec.x * 64) + lane);
            float fcur = (float)(rec.y & 0xFFFFu) * (1.0f / 65536.0f);

            #pragma unroll 1
            for (int e = b0; e < b1; e++) {
                // prefetch e+1
                const int en = (e + 1 < b1) ? e + 1 : e;
                uint2 recn = __ldg(g_rec + en);
                uint4 twn = __ldg(reinterpret_cast<const uint4*>(
                    g_tab2 + (size_t)(recn.y >> 16) * CH) + lane);
                uint2 hwn = __ldg(reinterpret_cast<const uint2*>(
                    g_h2 + (size_t)recn.x * 64) + lane);
                float fn = (float)(recn.y & 0xFFFFu) * (1.0f / 65536.0f);

                float2 p0 = __half22float2(*reinterpret_cast<__half2*>(&tw.x));
                float2 p1 = __half22float2(*reinterpret_cast<__half2*>(&tw.y));
                float2 p2 = __half22float2(*reinterpret_cast<__half2*>(&tw.z));
                float2 p3 = __half22float2(*reinterpret_cast<__half2*>(&tw.w));
                float2 h01 = __half22float2(*reinterpret_cast<__half2*>(&hw.x));
                float2 h23 = __half22float2(*reinterpret_cast<__half2*>(&hw.y));
                acc.x = fmaf(fmaf(fcur, p0.y - p0.x, p0.x), h01.x, acc.x);
                acc.y = fmaf(fmaf(fcur, p1.y - p1.x, p1.x), h01.y, acc.y);
                acc.z = fmaf(fmaf(fcur, p2.y - p2.x, p2.x), h23.x, acc.z);
                acc.w = fmaf(fmaf(fcur, p3.y - p3.x, p3.x), h23.y, acc.w);

                tw = twn; hw = hwn; fcur = fn;
            }
        }
        *reinterpret_cast<float4*>(g_agg + (size_t)n * CH + lane * 4) = acc;
    }
}

// ---------------------------------------------------------------------------
__global__ void tab2_kernel() {
    int idx = blockIdx.x * blockDim.x + threadIdx.x;
    if (idx < NTAB * CH) {
        int i = idx >> 7, c = idx & 127;
        float a = g_table[(size_t)i * CH + c];
        float b = g_table[(size_t)(i + 1) * CH + c];
        g_tab2[(size_t)i * CH + c] = __floats2half2_rn(a, b);
    }
}

__global__ void prep_pack_kernel(const float* __restrict__ W_lin,
                                 const float* __restrict__ Wm1,
                                 const float* __restrict__ Wm2)
{
    int idx = blockIdx.x * blockDim.x + threadIdx.x;
    if (idx >= 3 * 8192) return;
    int m = idx / 8192, r = idx - m * 8192;
    int lane = r & 31, jk = r >> 5;
    int kq = jk & 15, j = jk >> 4;
    int g = lane >> 2, t = lane & 3;
    int n = j * 8 + g, k0 = kq * 8;
    float b0, b1;
    if (m == 0) {
        b0 = W_lin[n * CH + k0 + t];
        b1 = W_lin[n * CH + k0 + 4 + t];
    } else {
        const float* Wm = (m == 1) ? Wm1 : Wm2;
        b0 = Wm[(k0 + t) * CH + n];
        b1 = Wm[(k0 + 4 + t) * CH + n];
    }
    uint32_t h0, l0, h1, l1;
    split_tf32(b0, h0, l0);
    split_tf32(b1, h1, l1);
    float4 v = make_float4(__uint_as_float(h0), __uint_as_float(h1),
                           __uint_as_float(l0), __uint_as_float(l1));
    if (m == 0) g_Wp0[r] = v; else if (m == 1) g_Wp1[r] = v; else g_Wp2[r] = v;
}

// ---------------------------------------------------------------------------
// 3xTF32 warp-MMA GEMM, weights from fragment-packed global image (L1-hot).
// ---------------------------------------------------------------------------
__device__ __forceinline__ void gemm_pk(const float* __restrict__ As,
                                        const float4* __restrict__ P,
                                        float* acc, int m0, int lane)
{
    const int g = lane >> 2, t = lane & 3;
    const float* arow0 = As + (m0 + g) * TS + t;
    const float* arow1 = As + (m0 + g + 8) * TS + t;
    #pragma unroll 1
    for (int kq = 0; kq < 16; kq++) {
        const int k0 = kq * 8;
        uint32_t ah[4], al[4];
        split_tf32(arow0[k0],     ah[0], al[0]);
        split_tf32(arow1[k0],     ah[1], al[1]);
        split_tf32(arow0[k0 + 4], ah[2], al[2]);
        split_tf32(arow1[k0 + 4], ah[3], al[3]);
        #pragma unroll
        for (int j = 0; j < 16; j++) {
            float4 w = __ldg(P + ((j << 4) + kq) * 32 + lane);
            uint32_t bh0 = __float_as_uint(w.x), bh1 = __float_as_uint(w.y);
            uint32_t bl0 = __float_as_uint(w.z), bl1 = __float_as_uint(w.w);
            float* c = acc + j * 4;
            MMA(c, ah[0], ah[1], ah[2], ah[3], bh0, bh1);
            MMA(c, al[0], al[1], al[2], al[3], bh0, bh1);
            MMA(c, ah[0], ah[1], ah[2], ah[3], bl0, bl1);
        }
    }
}

// ---------------------------------------------------------------------------
// h = features @ W_lin^T, emitted as fp16 pairs into g_h2.
// ---------------------------------------------------------------------------
__global__ __launch_bounds__(256, 2)
void node_linear_kernel(const float* __restrict__ feat)
{
    extern __shared__ float sm[];
    float* As = sm;                       // [128][TS]
    const int tid = threadIdx.x;
    const int lane = tid & 31;
    const int m0 = (tid >> 5) * 16;
    const int n0 = blockIdx.x * 128;

    for (int i = tid; i < 128 * 32; i += 256) {
        int r = i >> 5, k4 = i & 31;
        int n = n0 + r;
        float4 v = make_float4(0.f, 0.f, 0.f, 0.f);
        if (n < NN) v = reinterpret_cast<const float4*>(feat)[(size_t)n * 32 + k4];
        *reinterpret_cast<float4*>(As + r * TS + k4 * 4) = v;
    }
    __syncthreads();

    float acc[64];
    #pragma unroll
    for (int i = 0; i < 64; i++) acc[i] = 0.f;
    gemm_pk(As, g_Wp0, acc, m0, lane);
    __syncthreads();

    const int g = lane >> 2, t = lane & 3;
    #pragma unroll
    for (int j = 0; j < 16; j++) {
        int col = j * 8 + 2 * t;
        *reinterpret_cast<float2*>(As + (m0 + g) * TS + col)     = make_float2(acc[j*4+0], acc[j*4+1]);
        *reinterpret_cast<float2*>(As + (m0 + g + 8) * TS + col) = make_float2(acc[j*4+2], acc[j*4+3]);
    }
    __syncthreads();

    for (int i = tid; i < 128 * 16; i += 256) {
        int r = i >> 4, q = i & 15;
        int n = n0 + r;
        if (n < NN) {
            const float* src = As + r * TS + q * 8;
            __half2 h0 = __floats2half2_rn(src[0], src[1]);
            __half2 h1 = __floats2half2_rn(src[2], src[3]);
            __half2 h2 = __floats2half2_rn(src[4], src[5]);
            __half2 h3 = __floats2half2_rn(src[6], src[7]);
            uint4 pk = make_uint4(*(uint32_t*)&h0, *(uint32_t*)&h1,
                                  *(uint32_t*)&h2, *(uint32_t*)&h3);
            reinterpret_cast<uint4*>(g_h2)[(size_t)n * 16 + q] = pk;
        }
    }
}

// ---------------------------------------------------------------------------
// out = ssp(agg @ Wm1 + bm1) @ Wm2 + bm2
// ---------------------------------------------------------------------------
__global__ __launch_bounds__(256, 2)
void out_mlp_kernel(const float* __restrict__ bm1, const float* __restrict__ bm2,
                    float* __restrict__ out)
{
    extern __shared__ float sm[];
    float* As = sm;                       // [128][TS]
    float* bs = sm + 128 * TS;            // [128]
    const int tid = threadIdx.x;
    const int lane = tid & 31;
    const int m0 = (tid >> 5) * 16;
    const int n0 = blockIdx.x * 128;
    const int g = lane >> 2, t = lane & 3;

    if (tid < CH) bs[tid] = bm1[tid];
    for (int i = tid; i < 128 * 32; i += 256) {
        int r = i >> 5, k4 = i & 31;
        int n = n0 + r;
        float4 v = make_float4(0.f, 0.f, 0.f, 0.f);
        if (n < NN) v = reinterpret_cast<const float4*>(g_agg)[(size_t)n * 32 + k4];
        *reinterpret_cast<float4*>(As + r * TS + k4 * 4) = v;
    }
    __syncthreads();

    float acc[64];
    #pragma unroll
    for (int i = 0; i < 64; i++) acc[i] = 0.f;
    gemm_pk(As, g_Wp1, acc, m0, lane);
    __syncthreads();

    #pragma unroll
    for (int j = 0; j < 16; j++) {
        int col = j * 8 + 2 * t;
        float b0 = bs[col], b1 = bs[col + 1];
        *reinterpret_cast<float2*>(As + (m0 + g) * TS + col) =
            make_float2(ssp(acc[j*4+0] + b0), ssp(acc[j*4+1] + b1));
        *reinterpret_cast<float2*>(As + (m0 + g + 8) * TS + col) =
            make_float2(ssp(acc[j*4+2] + b0), ssp(acc[j*4+3] + b1));
    }
    __syncthreads();
    if (tid < CH) bs[tid] = bm2[tid];
    __syncthreads();

    #pragma unroll
    for (int i = 0; i < 64; i++) acc[i] = 0.f;
    gemm_pk(As, g_Wp2, acc, m0, lane);
    __syncthreads();

    #pragma unroll
    for (int j = 0; j < 16; j++) {
        int col = j * 8 + 2 * t;
        float b0 = bs[col], b1 = bs[col + 1];
        *reinterpret_cast<float2*>(As + (m0 + g) * TS + col) =
            make_float2(acc[j*4+0] + b0, acc[j*4+1] + b1);
        *reinterpret_cast<float2*>(As + (m0 + g + 8) * TS + col) =
            make_float2(acc[j*4+2] + b0, acc[j*4+3] + b1);
    }
    __syncthreads();

    for (int i = tid; i < 128 * 32; i += 256) {
        int r = i >> 5, k4 = i & 31;
        int n = n0 + r;
        if (n < NN)
            reinterpret_cast<float4*>(out)[(size_t)n * 32 + k4] =
                *reinterpret_cast<const float4*>(As + r * TS + k4 * 4);
    }
}

// ---------------------------------------------------------------------------
// Build table: ef(r_i), r_i = i*5/NTAB
// ---------------------------------------------------------------------------
__global__ __launch_bounds__(256, 1)
void table_kernel(const float* __restrict__ Wf1, const float* __restrict__ bf1,
                  const float* __restrict__ Wf2, const float* __restrict__ bf2)
{
    extern __shared__ float sm[];
    float* Wf1s  = sm;
    float* Wf2s  = Wf1s + FE * CH;
    float* bf1s  = Wf2s + CH * CH;
    float* bf2s  = bf1s + CH;
    float* basis = bf2s + CH;
    float* t1    = basis + 128 * 53;

    const int tid = threadIdx.x;
    const int e0 = blockIdx.x * 128;
    const float H = 5.0f / (float)NTAB;

    for (int i = tid; i < FE * CH; i += 256) Wf1s[i] = Wf1[i];
    for (int i = tid; i < CH * CH; i += 256) Wf2s[i] = Wf2[i];
    if (tid < CH) { bf1s[tid] = bf1[tid]; bf2s[tid] = bf2[tid]; }

    const float delta = 5.0f / 49.0f;
    const float coef  = 2401.0f / 50.0f;
    for (int i = tid; i < 128 * FE; i += 256) {
        int e = i / FE, f = i - e * FE;
        float r = (float)(e0 + e) * H;
        float d = r - delta * (float)f;
        basis[e * 53 + f] = __expf(-coef * d * d);
    }
    __syncthreads();

    const int ei = tid >> 4;
    const int c0 = (tid & 15) * 8;

    float acc[8][8];
    #pragma unroll
    for (int r = 0; r < 8; r++)
        #pragma unroll
        for (int j = 0; j < 8; j++) acc[r][j] = bf1s[c0 + j];

    #pragma unroll 2
    for (int f = 0; f < FE; f++) {
        float a[8];
        #pragma unroll
        for (int r = 0; r < 8; r++) a[r] = basis[(ei * 8 + r) * 53 + f];
        float4 w0 = *reinterpret_cast<const float4*>(Wf1s + f * CH + c0);
        float4 w1 = *reinterpret_cast<const float4*>(Wf1s + f * CH + c0 + 4);
        #pragma unroll
        for (int r = 0; r < 8; r++) { FMA8(acc[r], a[r], w0, w1); }
    }
    #pragma unroll
    for (int r = 0; r < 8; r++)
        #pragma unroll
        for (int j = 0; j < 8; j++)
            t1[(ei * 8 + r) * 130 + c0 + j] = ssp(acc[r][j]);
    __syncthreads();

    #pragma unroll
    for (int r = 0; r < 8; r++)
        #pragma unroll
        for (int j = 0; j < 8; j++) acc[r][j] = bf2s[c0 + j];

    #pragma unroll 2
    for (int k = 0; k < CH; k++) {
        float a[8];
        #pragma unroll
        for (int r = 0; r < 8; r++) a[r] = t1[(ei * 8 + r) * 130 + k];
        float4 w0 = *reinterpret_cast<const float4*>(Wf2s + k * CH + c0);
        float4 w1 = *reinterpret_cast<const float4*>(Wf2s + k * CH + c0 + 4);
        #pragma unroll
        for (int r = 0; r < 8; r++) { FMA8(acc[r], a[r], w0, w1); }
    }

    #pragma unroll
    for (int r = 0; r < 8; r++) {
        int row = e0 + ei * 8 + r;
        if (row <= NTAB) {
            float* dst = g_table + (size_t)row * CH + c0;
            *reinterpret_cast<float4*>(dst)     = make_float4(acc[r][0], acc[r][1], acc[r][2], acc[r][3]);
            *reinterpret_cast<float4*>(dst + 4) = make_float4(acc[r][4], acc[r][5], acc[r][6], acc[r][7]);
        }
    }
}

// ---------------------------------------------------------------------------
extern "C" void kernel_launch(void* const* d_in, const int* in_sizes, int n_in,
                              void* d_out, int out_size)
{
    const float* features = (const float*)d_in[0];
    const float* dist     = (const float*)d_in[1];
    const float* W_lin    = (const float*)d_in[2];
    const float* Wf1      = (const float*)d_in[3];
    const float* bf1      = (const float*)d_in[4];
    const float* Wf2      = (const float*)d_in[5];
    const float* bf2      = (const float*)d_in[6];
    const float* Wm1      = (const float*)d_in[7];
    const float* bm1      = (const float*)d_in[8];
    const float* Wm2      = (const float*)d_in[9];
    const float* bm2      = (const float*)d_in[10];
    const int*   senders   = (const int*)d_in[11];
    const int*   receivers = (const int*)d_in[12];
    float* out = (float*)d_out;

    const int smemA = 128 * TS * 4;
    const int smemT = (FE * CH + CH * CH + 2 * CH + 128 * 53 + 128 * 130) * 4;
    const int smemC = (128 * TS + CH) * 4;

    cudaFuncSetAttribute(node_linear_kernel, cudaFuncAttributeMaxDynamicSharedMemorySize, smemA);
    cudaFuncSetAttribute(table_kernel,       cudaFuncAttributeMaxDynamicSharedMemorySize, smemT);
    cudaFuncSetAttribute(out_mlp_kernel,     cudaFuncAttributeMaxDynamicSharedMemorySize, smemC);

    // CSR build path (independent of table/node paths except fill->gather)
    zero_count_kernel<<<(NN + 255) / 256, 256>>>();
    count_kernel<<<1024, 256>>>(receivers);
    scan_kernel<<<1, 1024>>>();
    fill_kernel<<<1024, 256>>>(dist, senders, receivers);

    table_kernel<<<(NTAB + 1 + 127) / 128, 256, smemT>>>(Wf1, bf1, Wf2, bf2);
    tab2_kernel<<<(NTAB * CH + 255) / 256, 256>>>();
    prep_pack_kernel<<<96, 256>>>(W_lin, Wm1, Wm2);
    node_linear_kernel<<<(NN + 127) / 128, 256, smemA>>>(features);

    gather_kernel<<<1024, 256>>>();
    out_mlp_kernel<<<(NN + 127) / 128, 256, smemC>>>(bm1, bm2, out);
}